// round 8
// baseline (speedup 1.0000x reference)
#include <cuda_runtime.h>
#include <math.h>

#define FULL 0xffffffffu
#define NMAT 38400
#define WPB 4

// 38400 * 576 = 22118400 floats (88.5 MB) each — allowed __device__ scratch
__device__ float g_s1[22118400];
__device__ float g_s2[22118400];

// ---------------------------------------------------------------------------
// Warp-level parallel Jacobi eigensolver for a symmetric 24x24 matrix,
// with deferred column scaling (tangent form).
// Lane j (j<24) holds column j of B in b[24] and column j of V in v[24],
// where true A = B * diag(d) and true V = Vreg * diag(d) (V shares the same
// per-column scale because both accumulate identical products of c).
// Column update is a single FFMA per element: b += coeff * b_partner with
// coeff = +/- t * d_q / d_j;  d *= c each round;  rescaled every sweep.
// Row update (true c,s) is unaffected: diag(d) commutes on the right.
// Round-robin ordering: 12 disjoint pairs/round, 23 rounds/sweep, unrolled.
// On exit: v (true scale) = eigenvector columns, wout = eigenvalue (true dp).
// ---------------------------------------------------------------------------
template <int NS>
__device__ __forceinline__ void jacobi24(float (&b)[24], float (&v)[24],
                                         float &wout, int lane) {
#pragma unroll
  for (int i = 0; i < 24; i++) v[i] = (i == lane) ? 1.f : 0.f;
  float dp = 0.f;
#pragma unroll
  for (int i = 0; i < 24; i++) dp = (lane == i) ? b[i] : dp;

  float d = 1.f, rinv = 1.f;  // column scale and its reciprocal

  for (int sweep = 0; sweep < NS; sweep++) {
#pragma unroll
    for (int r = 0; r < 23; r++) {
      int partner;
      if (lane >= 24)      partner = lane;
      else if (lane == 23) partner = r;
      else if (lane == r)  partner = 23;
      else                 partner = (2 * r + 23 - lane) % 23;

      // apq (true scale) = element `partner` of own column * d
      float ob = 0.f;
#pragma unroll
      for (int i = 0; i < 24; i++) ob = (partner == i) ? b[i] : ob;
      float apq = ob * d;

      float dq = __shfl_sync(FULL, dp, partner);
      bool  isLow = lane <= partner;
      int   low   = isLow ? lane : partner;
      float app   = isLow ? dp : dq;
      float aqq   = isLow ? dq : dp;
      apq = __shfl_sync(FULL, apq, low);  // identical on both pair lanes

      float c, s, tt, h;
      if (fabsf(apq) > 1e-30f) {
        float tau = (aqq - app) / (2.0f * apq);
        tt = ((tau >= 0.f) ? 1.f : -1.f) /
             (fabsf(tau) + sqrtf(fmaf(tau, tau, 1.f)));
        h = fmaf(tt, tt, 1.f);
        c = rsqrtf(h);
        s = tt * c;
      } else { c = 1.f; s = 0.f; tt = 0.f; h = 1.f; }

      // scaled single-FFMA column update coefficient
      float dscale_q = __shfl_sync(FULL, d, partner);
      float tse = isLow ? -tt : tt;
      float coeff = tse * dscale_q * rinv;

      dp = isLow ? fmaf(-tt, apq, app) : fmaf(tt, apq, aqq);

      // column update B <- "B*J" (scaled), V <- "V*J" (same scale)
#pragma unroll
      for (int i = 0; i < 24; i++) {
        float bb = __shfl_sync(FULL, b[i], partner);
        b[i] = fmaf(coeff, bb, b[i]);
        float bv = __shfl_sync(FULL, v[i], partner);
        v[i] = fmaf(coeff, bv, v[i]);
      }
      d *= c;
      rinv *= h * c;  // 1/c = h*c since c = rsqrt(h)

      // row update A <- J^T * A (true c,s; scale-invariant): 12 disjoint pairs
#pragma unroll
      for (int k = 0; k < 12; k++) {
        int p = (k == 0) ? r : (r + k) % 23;
        int q = (k == 0) ? 23 : (r + 23 - k) % 23;
        int P = p < q ? p : q;
        int Q = p < q ? q : p;
        float ck = __shfl_sync(FULL, c, P);
        float sk = __shfl_sync(FULL, s, P);
        float xP = b[P], xQ = b[Q];
        b[P] = fmaf(-sk, xQ, ck * xP);
        b[Q] = fmaf( sk, xP, ck * xQ);
      }
    }
    // fold the deferred scale back in once per sweep (keeps d well above
    // fp32 underflow: worst case 0.707^23 ~ 3e-4 per sweep)
#pragma unroll
    for (int i = 0; i < 24; i++) { b[i] *= d; v[i] *= d; }
    d = 1.f; rinv = 1.f;
  }
  wout = dp;  // incrementally-maintained true-scale diagonal
}

// ---------------------------------------------------------------------------
// R = U * diag(f) * U^T.  u = columns (lane j holds col j), f = per-lane scalar.
// DESTROYS u (scales it by f). tb = per-warp smem scratch (>= 600 floats).
// ---------------------------------------------------------------------------
__device__ __forceinline__ void recompose24(float (&u)[24], float f,
                                            float (&r)[24], int lane, float *tb) {
  __syncwarp();
  if (lane < 24) {
#pragma unroll
    for (int i = 0; i < 24; i++) tb[lane * 25 + i] = u[i];  // tb[col*25+row]
  }
  __syncwarp();
  int ln = (lane < 24) ? lane : 0;
#pragma unroll
  for (int i = 0; i < 24; i++) { u[i] *= f; r[i] = 0.f; }   // u := U diag(f)
#pragma unroll
  for (int k = 0; k < 24; k++) {
    float coef = tb[k * 25 + ln];        // U[lane][k], conflict-free LDS
#pragma unroll
    for (int i = 0; i < 24; i++)
      r[i] = fmaf(__shfl_sync(FULL, u[i], k), coef, r[i]);
  }
  __syncwarp();
}

// ---------------------------------------------------------------------------
// K1: x -> sym_logm(x) into g_s1. One warp per matrix.
// ---------------------------------------------------------------------------
__global__ void __launch_bounds__(128) k_logm(const float *__restrict__ x) {
  __shared__ float tbuf[WPB][600];
  int wid = threadIdx.x >> 5, lane = threadIdx.x & 31;
  int m = blockIdx.x * WPB + wid;
  const float *src = x + (size_t)m * 576;

  float a[24];
#pragma unroll
  for (int i = 0; i < 24; i++) a[i] = (lane < 24) ? src[i * 24 + lane] : 0.f;

  float v[24], w;
  jacobi24<5>(a, v, w, lane);
  float f = logf(fmaxf(w, 1e-12f));
  float r[24];
  recompose24(v, f, r, lane, tbuf[wid]);

  float *dst = g_s1 + (size_t)m * 576;
  if (lane < 24) {
#pragma unroll
    for (int i = 0; i < 24; i++) dst[i * 24 + lane] = r[i];
  }
}

// ---------------------------------------------------------------------------
// K2: tangent-space aggregation.
// g_s2[g, j] = sum_v A[g, v, j] * g_s1[g, v]
// ---------------------------------------------------------------------------
__global__ void __launch_bounds__(800) k_agg(const float *__restrict__ A) {
  __shared__ float As[625];
  int g = blockIdx.x;
  for (int e = threadIdx.x; e < 625; e += 800) As[e] = A[(size_t)g * 625 + e];
  __syncthreads();

  int j = threadIdx.x >> 5;
  int lane = threadIdx.x & 31;
  float av[25];
#pragma unroll
  for (int vv = 0; vv < 25; vv++) av[vv] = As[vv * 25 + j];

  const float *src = g_s1 + (size_t)g * 14400;
  float *dst = g_s2 + ((size_t)g * 25 + j) * 576;
  for (int it = 0; it < 18; it++) {
    int idx = lane + it * 32;
    float acc = 0.f;
#pragma unroll
    for (int vv = 0; vv < 25; vv++)
      acc = fmaf(av[vv], __ldg(src + vv * 576 + idx), acc);
    dst[idx] = acc;
  }
}

// ---------------------------------------------------------------------------
// K3: expm + congruence fused via U = W*V:
//   Z = W expm(L) W^T = (W V) diag(exp w) (W V)^T
// then Frobenius-normalize, powm(0.5). One warp per matrix.
// W is matrix-independent -> broadcast from smem, no shuffles for U = W*V.
// ---------------------------------------------------------------------------
__global__ void __launch_bounds__(128) k_final(const float *__restrict__ Wm,
                                               float *__restrict__ out) {
  __shared__ float tbuf[WPB][600];
  __shared__ float Ws[576];
  for (int t = threadIdx.x; t < 576; t += 128) Ws[t] = Wm[t];
  __syncthreads();

  int wid = threadIdx.x >> 5, lane = threadIdx.x & 31;
  int m = blockIdx.x * WPB + wid;

  const float *src = g_s2 + (size_t)m * 576;
  float a[24];
#pragma unroll
  for (int i = 0; i < 24; i++) a[i] = (lane < 24) ? src[i * 24 + lane] : 0.f;

  // eig of aggregated log-matrix
  float v[24], w;
  jacobi24<5>(a, v, w, lane);
  float f = expf(w);

  // U = W * V : u[i] = sum_k W[i][k] * v[k]; W broadcast from smem (no shfl)
  float u[24];
#pragma unroll
  for (int i = 0; i < 24; i++) {
    float acc = 0.f;
    const float4 *wr = (const float4 *)&Ws[i * 24];
#pragma unroll
    for (int k4 = 0; k4 < 6; k4++) {
      float4 w4 = wr[k4];
      acc = fmaf(w4.x, v[k4 * 4 + 0], acc);
      acc = fmaf(w4.y, v[k4 * 4 + 1], acc);
      acc = fmaf(w4.z, v[k4 * 4 + 2], acc);
      acc = fmaf(w4.w, v[k4 * 4 + 3], acc);
    }
    u[i] = acc;
  }

  // Z = U diag(f) U^T  (destroys u)
  float z[24];
  recompose24(u, f, z, lane, tbuf[wid]);

  // Frobenius normalization
  float ss = 0.f;
  if (lane < 24) {
#pragma unroll
    for (int i = 0; i < 24; i++) ss = fmaf(z[i], z[i], ss);
  }
#pragma unroll
  for (int off = 16; off > 0; off >>= 1) ss += __shfl_xor_sync(FULL, ss, off);
  float inv = rsqrtf(ss);

#pragma unroll
  for (int i = 0; i < 24; i++) a[i] = (lane < 24) ? z[i] * inv : 0.f;

  // powm 0.5 — 6 sweeps: small-eigenvalue sqrt amplifies residual, needs margin
  jacobi24<6>(a, v, w, lane);
  float fs = sqrtf(fmaxf(w, 1e-12f));
  float r[24];
  recompose24(v, fs, r, lane, tbuf[wid]);

  float *dst = out + (size_t)m * 576;
  if (lane < 24) {
#pragma unroll
    for (int i = 0; i < 24; i++) dst[i * 24 + lane] = r[i];
  }
}

// ---------------------------------------------------------------------------
extern "C" void kernel_launch(void *const *d_in, const int *in_sizes, int n_in,
                              void *d_out, int out_size) {
  const float *x = nullptr, *A = nullptr, *Wm = nullptr;
  for (int i = 0; i < n_in; i++) {
    if (in_sizes[i] == 22118400)     x  = (const float *)d_in[i];
    else if (in_sizes[i] == 960000)  A  = (const float *)d_in[i];
    else if (in_sizes[i] == 576)     Wm = (const float *)d_in[i];
  }
  float *out = (float *)d_out;

  k_logm<<<NMAT / WPB, 128>>>(x);
  k_agg<<<1536, 800>>>(A);
  k_final<<<NMAT / WPB, 128>>>(Wm, out);
}

// round 10
// speedup vs baseline: 1.0777x; 1.0777x over previous
#include <cuda_runtime.h>
#include <math.h>

#define FULL 0xffffffffu
#define NMAT 38400
#define WPB 4

// 38400 * 576 = 22118400 floats (88.5 MB) each — allowed __device__ scratch
__device__ float g_s1[22118400];
__device__ float g_s2[22118400];

// ---------------------------------------------------------------------------
// Warp-level parallel Jacobi eigensolver for a symmetric 24x24 matrix.
// Lane j (j<24) holds column j of A in a[24] and column j of V in v[24].
// Round-robin ordering: 12 disjoint pairs per round, 23 rounds per sweep.
// Rounds fully unrolled -> all register indices compile-time (no spills).
// On exit: v = eigenvector columns, wout = eigenvalue of this lane's column.
// (Two-sided: absolute accuracy eps*||A||; the one-sided variant was tried
//  and rejected — it squares the condition number via the implicit Gram.)
// ---------------------------------------------------------------------------
template <int NS>
__device__ __forceinline__ void jacobi24(float (&a)[24], float (&v)[24],
                                         float &wout, int lane) {
#pragma unroll
  for (int i = 0; i < 24; i++) v[i] = (i == lane) ? 1.f : 0.f;
  float dp = 0.f;
#pragma unroll
  for (int i = 0; i < 24; i++) dp = (lane == i) ? a[i] : dp;

  for (int sweep = 0; sweep < NS; sweep++) {
#pragma unroll
    for (int r = 0; r < 23; r++) {
      int partner;
      if (lane >= 24)      partner = lane;
      else if (lane == 23) partner = r;
      else if (lane == r)  partner = 23;
      else                 partner = (2 * r + 23 - lane) % 23;

      // apq = A[partner][lane] : element `partner` of own column
      float apq = 0.f;
#pragma unroll
      for (int i = 0; i < 24; i++) apq = (partner == i) ? a[i] : apq;

      float dq = __shfl_sync(FULL, dp, partner);
      bool  isLow = lane <= partner;
      int   low   = isLow ? lane : partner;
      float app   = isLow ? dp : dq;
      float aqq   = isLow ? dq : dp;
      apq = __shfl_sync(FULL, apq, low);  // identical c,s on both lanes

      float c, s, tt;
      if (fabsf(apq) > 1e-30f) {
        float tau = (aqq - app) / (2.0f * apq);
        tt = ((tau >= 0.f) ? 1.f : -1.f) /
             (fabsf(tau) + sqrtf(fmaf(tau, tau, 1.f)));
        c = rsqrtf(fmaf(tt, tt, 1.f));
        s = tt * c;
      } else { c = 1.f; s = 0.f; tt = 0.f; }

      dp = isLow ? fmaf(-tt, apq, app) : fmaf(tt, apq, aqq);

      // column update A <- A*J, V <- V*J
      float se = isLow ? -s : s;
#pragma unroll
      for (int i = 0; i < 24; i++) {
        float b  = __shfl_sync(FULL, a[i], partner);
        a[i] = fmaf(se, b, c * a[i]);
        float bv = __shfl_sync(FULL, v[i], partner);
        v[i] = fmaf(se, bv, c * v[i]);
      }

      // row update A <- J^T * A : 12 disjoint pairs, compile-time indices
#pragma unroll
      for (int k = 0; k < 12; k++) {
        int p = (k == 0) ? r : (r + k) % 23;
        int q = (k == 0) ? 23 : (r + 23 - k) % 23;
        int P = p < q ? p : q;
        int Q = p < q ? q : p;
        float ck = __shfl_sync(FULL, c, P);
        float sk = __shfl_sync(FULL, s, P);
        float xP = a[P], xQ = a[Q];
        a[P] = fmaf(-sk, xQ, ck * xP);
        a[Q] = fmaf( sk, xP, ck * xQ);
      }
    }
  }
  float wl = 0.f;
#pragma unroll
  for (int i = 0; i < 24; i++) wl = (lane == i) ? a[i] : wl;
  wout = wl;
}

// ---------------------------------------------------------------------------
// R = U * diag(f) * U^T.  u = columns (lane j holds col j), f = per-lane scalar.
// DESTROYS u (scales it by f). tb = per-warp smem scratch (>= 600 floats);
// transposed factor re-read from smem in the k-loop (small live set).
// ---------------------------------------------------------------------------
__device__ __forceinline__ void recompose24(float (&u)[24], float f,
                                            float (&r)[24], int lane, float *tb) {
  __syncwarp();
  if (lane < 24) {
#pragma unroll
    for (int i = 0; i < 24; i++) tb[lane * 25 + i] = u[i];  // tb[col*25+row]
  }
  __syncwarp();
  int ln = (lane < 24) ? lane : 0;
#pragma unroll
  for (int i = 0; i < 24; i++) { u[i] *= f; r[i] = 0.f; }   // u := U diag(f)
#pragma unroll
  for (int k = 0; k < 24; k++) {
    float coef = tb[k * 25 + ln];        // U[lane][k], conflict-free LDS
#pragma unroll
    for (int i = 0; i < 24; i++)
      r[i] = fmaf(__shfl_sync(FULL, u[i], k), coef, r[i]);
  }
  __syncwarp();
}

// ---------------------------------------------------------------------------
// K1: x -> sym_logm(x) into g_s1. One warp per matrix.
// ---------------------------------------------------------------------------
__global__ void __launch_bounds__(128) k_logm(const float *__restrict__ x) {
  __shared__ float tbuf[WPB][600];
  int wid = threadIdx.x >> 5, lane = threadIdx.x & 31;
  int m = blockIdx.x * WPB + wid;
  const float *src = x + (size_t)m * 576;

  float a[24];
#pragma unroll
  for (int i = 0; i < 24; i++) a[i] = (lane < 24) ? src[i * 24 + lane] : 0.f;

  float v[24], w;
  jacobi24<5>(a, v, w, lane);
  float f = logf(fmaxf(w, 1e-12f));
  float r[24];
  recompose24(v, f, r, lane, tbuf[wid]);

  float *dst = g_s1 + (size_t)m * 576;
  if (lane < 24) {
#pragma unroll
    for (int i = 0; i < 24; i++) dst[i * 24 + lane] = r[i];
  }
}

// ---------------------------------------------------------------------------
// K2: tangent-space aggregation.
// g_s2[g, j] = sum_v A[g, v, j] * g_s1[g, v]
// ---------------------------------------------------------------------------
__global__ void __launch_bounds__(800) k_agg(const float *__restrict__ A) {
  __shared__ float As[625];
  int g = blockIdx.x;
  for (int e = threadIdx.x; e < 625; e += 800) As[e] = A[(size_t)g * 625 + e];
  __syncthreads();

  int j = threadIdx.x >> 5;
  int lane = threadIdx.x & 31;
  float av[25];
#pragma unroll
  for (int vv = 0; vv < 25; vv++) av[vv] = As[vv * 25 + j];

  const float *src = g_s1 + (size_t)g * 14400;
  float *dst = g_s2 + ((size_t)g * 25 + j) * 576;
  for (int it = 0; it < 18; it++) {
    int idx = lane + it * 32;
    float acc = 0.f;
#pragma unroll
    for (int vv = 0; vv < 25; vv++)
      acc = fmaf(av[vv], __ldg(src + vv * 576 + idx), acc);
    dst[idx] = acc;
  }
}

// ---------------------------------------------------------------------------
// K3: expm + congruence fused via U = W*V:
//   Z = W expm(L) W^T = (W V) diag(exp w) (W V)^T
// then Frobenius-normalize, powm(0.5). One warp per matrix.
// W is matrix-independent -> broadcast from smem, no shuffles for U = W*V.
// ---------------------------------------------------------------------------
__global__ void __launch_bounds__(128) k_final(const float *__restrict__ Wm,
                                               float *__restrict__ out) {
  __shared__ float tbuf[WPB][600];
  __shared__ float Ws[576];
  for (int t = threadIdx.x; t < 576; t += 128) Ws[t] = Wm[t];
  __syncthreads();

  int wid = threadIdx.x >> 5, lane = threadIdx.x & 31;
  int m = blockIdx.x * WPB + wid;

  const float *src = g_s2 + (size_t)m * 576;
  float a[24];
#pragma unroll
  for (int i = 0; i < 24; i++) a[i] = (lane < 24) ? src[i * 24 + lane] : 0.f;

  // eig of aggregated log-matrix
  float v[24], w;
  jacobi24<5>(a, v, w, lane);
  float f = expf(w);

  // U = W * V : u[i] = sum_k W[i][k] * v[k]; W broadcast from smem (no shfl)
  float u[24];
#pragma unroll
  for (int i = 0; i < 24; i++) {
    float acc = 0.f;
    const float4 *wr = (const float4 *)&Ws[i * 24];
#pragma unroll
    for (int k4 = 0; k4 < 6; k4++) {
      float4 w4 = wr[k4];
      acc = fmaf(w4.x, v[k4 * 4 + 0], acc);
      acc = fmaf(w4.y, v[k4 * 4 + 1], acc);
      acc = fmaf(w4.z, v[k4 * 4 + 2], acc);
      acc = fmaf(w4.w, v[k4 * 4 + 3], acc);
    }
    u[i] = acc;
  }

  // Z = U diag(f) U^T  (destroys u)
  float z[24];
  recompose24(u, f, z, lane, tbuf[wid]);

  // Frobenius normalization
  float ss = 0.f;
  if (lane < 24) {
#pragma unroll
    for (int i = 0; i < 24; i++) ss = fmaf(z[i], z[i], ss);
  }
#pragma unroll
  for (int off = 16; off > 0; off >>= 1) ss += __shfl_xor_sync(FULL, ss, off);
  float inv = rsqrtf(ss);

#pragma unroll
  for (int i = 0; i < 24; i++) a[i] = (lane < 24) ? z[i] * inv : 0.f;

  // powm 0.5 — 6 sweeps: small-eigenvalue sqrt amplifies residual (30-60x),
  // calibrated: 5/5/6 -> 3.8e-5, 5/5/5 -> 6.5e-4. Do not reduce.
  jacobi24<6>(a, v, w, lane);
  float fs = sqrtf(fmaxf(w, 1e-12f));
  float r[24];
  recompose24(v, fs, r, lane, tbuf[wid]);

  float *dst = out + (size_t)m * 576;
  if (lane < 24) {
#pragma unroll
    for (int i = 0; i < 24; i++) dst[i * 24 + lane] = r[i];
  }
}

// ---------------------------------------------------------------------------
extern "C" void kernel_launch(void *const *d_in, const int *in_sizes, int n_in,
                              void *d_out, int out_size) {
  const float *x = nullptr, *A = nullptr, *Wm = nullptr;
  for (int i = 0; i < n_in; i++) {
    if (in_sizes[i] == 22118400)     x  = (const float *)d_in[i];
    else if (in_sizes[i] == 960000)  A  = (const float *)d_in[i];
    else if (in_sizes[i] == 576)     Wm = (const float *)d_in[i];
  }
  float *out = (float *)d_out;

  k_logm<<<NMAT / WPB, 128>>>(x);
  k_agg<<<1536, 800>>>(A);
  k_final<<<NMAT / WPB, 128>>>(Wm, out);
}

// round 11
// speedup vs baseline: 1.3359x; 1.2396x over previous
#include <cuda_runtime.h>
#include <math.h>

#define FULL 0xffffffffu
#define NMAT 38400
#define WPB 4

// 38400 * 576 = 22118400 floats (88.5 MB) each — allowed __device__ scratch
__device__ float g_s1[22118400];
__device__ float g_s2[22118400];

// ---------------------------------------------------------------------------
// Two-sided warp-parallel Jacobi eigensolver, symmetric 24x24.
// Lane j (j<24) holds column j of A in a[24] and column j of V in v[24].
// Round-robin: 12 disjoint pairs/round, 23 rounds/sweep, fully unrolled.
// On exit: v = eigenvector columns, wout = eigenvalue of this lane's column.
// ---------------------------------------------------------------------------
template <int NS>
__device__ __forceinline__ void jacobi24(float (&a)[24], float (&v)[24],
                                         float &wout, int lane) {
#pragma unroll
  for (int i = 0; i < 24; i++) v[i] = (i == lane) ? 1.f : 0.f;
  float dp = 0.f;
#pragma unroll
  for (int i = 0; i < 24; i++) dp = (lane == i) ? a[i] : dp;

  for (int sweep = 0; sweep < NS; sweep++) {
#pragma unroll
    for (int r = 0; r < 23; r++) {
      int partner;
      if (lane >= 24)      partner = lane;
      else if (lane == 23) partner = r;
      else if (lane == r)  partner = 23;
      else                 partner = (2 * r + 23 - lane) % 23;

      float apq = 0.f;
#pragma unroll
      for (int i = 0; i < 24; i++) apq = (partner == i) ? a[i] : apq;

      float dq = __shfl_sync(FULL, dp, partner);
      bool  isLow = lane <= partner;
      int   low   = isLow ? lane : partner;
      float app   = isLow ? dp : dq;
      float aqq   = isLow ? dq : dp;
      apq = __shfl_sync(FULL, apq, low);  // identical c,s on both lanes

      float c, s, tt;
      if (fabsf(apq) > 1e-30f) {
        float tau = (aqq - app) / (2.0f * apq);
        tt = ((tau >= 0.f) ? 1.f : -1.f) /
             (fabsf(tau) + sqrtf(fmaf(tau, tau, 1.f)));
        c = rsqrtf(fmaf(tt, tt, 1.f));
        s = tt * c;
      } else { c = 1.f; s = 0.f; tt = 0.f; }

      dp = isLow ? fmaf(-tt, apq, app) : fmaf(tt, apq, aqq);

      float se = isLow ? -s : s;
#pragma unroll
      for (int i = 0; i < 24; i++) {
        float b  = __shfl_sync(FULL, a[i], partner);
        a[i] = fmaf(se, b, c * a[i]);
        float bv = __shfl_sync(FULL, v[i], partner);
        v[i] = fmaf(se, bv, c * v[i]);
      }

#pragma unroll
      for (int k = 0; k < 12; k++) {
        int p = (k == 0) ? r : (r + k) % 23;
        int q = (k == 0) ? 23 : (r + 23 - k) % 23;
        int P = p < q ? p : q;
        int Q = p < q ? q : p;
        float ck = __shfl_sync(FULL, c, P);
        float sk = __shfl_sync(FULL, s, P);
        float xP = a[P], xQ = a[Q];
        a[P] = fmaf(-sk, xQ, ck * xP);
        a[Q] = fmaf( sk, xP, ck * xQ);
      }
    }
  }
  float wl = 0.f;
#pragma unroll
  for (int i = 0; i < 24; i++) wl = (lane == i) ? a[i] : wl;
  wout = wl;
}

// ---------------------------------------------------------------------------
// One-sided Jacobi column orthogonalization (SVD) of a 24x24 factor M.
// Lane j holds column j in b[24]. On exit, columns are mutually orthogonal:
// column j = sigma_k * h_k (singular value * unit left-singular-vector).
// Gram of M is Z = M M^T, so sigma^2 = eigenvalue of Z and sigma = sqrt(eig)
// DIRECTLY (no sqrt-amplification of rotation residuals). Valid here because
// M is an explicit factor (unlike R8's misuse on a symmetric matrix, where
// the implicit Gram A^2 squared the condition number).
// No V accumulation, no row update: ~115 instr/round vs ~270 two-sided.
// ---------------------------------------------------------------------------
template <int NS>
__device__ __forceinline__ void jacobi1s(float (&b)[24], int lane) {
  float app = 0.f;
#pragma unroll
  for (int i = 0; i < 24; i++) app = fmaf(b[i], b[i], app);

  for (int sweep = 0; sweep < NS; sweep++) {
#pragma unroll
    for (int r = 0; r < 23; r++) {
      int partner;
      if (lane >= 24)      partner = lane;
      else if (lane == 23) partner = r;
      else if (lane == r)  partner = 23;
      else                 partner = (2 * r + 23 - lane) % 23;

      float bp[24];
      float d0 = 0.f, d1 = 0.f, d2 = 0.f;
#pragma unroll
      for (int i = 0; i < 24; i += 3) {
        bp[i]     = __shfl_sync(FULL, b[i],     partner);
        d0 = fmaf(b[i],     bp[i],     d0);
        bp[i + 1] = __shfl_sync(FULL, b[i + 1], partner);
        d1 = fmaf(b[i + 1], bp[i + 1], d1);
        bp[i + 2] = __shfl_sync(FULL, b[i + 2], partner);
        d2 = fmaf(b[i + 2], bp[i + 2], d2);
      }
      float apq = (d0 + d1) + d2;           // identical on both pair lanes
      float nq  = __shfl_sync(FULL, app, partner);
      bool  isLow = lane <= partner;
      float nlow  = isLow ? app : nq;
      float nhigh = isLow ? nq : app;

      float c, s, tt;
      if (fabsf(apq) > 1e-30f) {
        float tau = (nhigh - nlow) / (2.0f * apq);
        tt = ((tau >= 0.f) ? 1.f : -1.f) /
             (fabsf(tau) + sqrtf(fmaf(tau, tau, 1.f)));
        c = rsqrtf(fmaf(tt, tt, 1.f));
        s = tt * c;
      } else { c = 1.f; s = 0.f; tt = 0.f; }

      float tse = isLow ? -tt : tt;
      app = fmaf(tse, apq, app);            // norm^2 update (exact Jacobi law)
      float se = isLow ? -s : s;
#pragma unroll
      for (int i = 0; i < 24; i++)
        b[i] = fmaf(se, bp[i], c * b[i]);   // own-column rotation only
    }
  }
}

// ---------------------------------------------------------------------------
// R = U * diag(f) * U^T.  u = columns (lane j holds col j), f = per-lane
// scalar. Non-destructive (R4 version — fastest measured).
// tb = per-warp smem scratch (>= 600 floats) to transpose U.
// ---------------------------------------------------------------------------
__device__ __forceinline__ void recompose24(const float (&u)[24], float f,
                                            float (&r)[24], int lane, float *tb) {
  __syncwarp();
  if (lane < 24) {
#pragma unroll
    for (int i = 0; i < 24; i++) tb[lane * 25 + i] = u[i];
  }
  __syncwarp();
  float ut[24];
  int ln = (lane < 24) ? lane : 0;
#pragma unroll
  for (int i = 0; i < 24; i++) ut[i] = tb[i * 25 + ln];

  float m[24];
#pragma unroll
  for (int i = 0; i < 24; i++) { m[i] = u[i] * f; r[i] = 0.f; }
#pragma unroll
  for (int k = 0; k < 24; k++) {
    float coef = ut[k];
#pragma unroll
    for (int i = 0; i < 24; i++)
      r[i] = fmaf(__shfl_sync(FULL, m[i], k), coef, r[i]);
  }
  __syncwarp();
}

// ---------------------------------------------------------------------------
// K1: x -> sym_logm(x) into g_s1. One warp per matrix. (R4 structure.)
// ---------------------------------------------------------------------------
__global__ void __launch_bounds__(128) k_logm(const float *__restrict__ x) {
  __shared__ float tbuf[WPB][600];
  int wid = threadIdx.x >> 5, lane = threadIdx.x & 31;
  int m = blockIdx.x * WPB + wid;
  const float *src = x + (size_t)m * 576;

  float a[24];
#pragma unroll
  for (int i = 0; i < 24; i++) a[i] = (lane < 24) ? src[i * 24 + lane] : 0.f;

  float v[24], w;
  jacobi24<5>(a, v, w, lane);
  float f = logf(fmaxf(w, 1e-12f));
  float r[24];
  recompose24(v, f, r, lane, tbuf[wid]);

  float *dst = g_s1 + (size_t)m * 576;
  if (lane < 24) {
#pragma unroll
    for (int i = 0; i < 24; i++) dst[i * 24 + lane] = r[i];
  }
}

// ---------------------------------------------------------------------------
// K2: tangent-space aggregation.
// ---------------------------------------------------------------------------
__global__ void __launch_bounds__(800) k_agg(const float *__restrict__ A) {
  __shared__ float As[625];
  int g = blockIdx.x;
  for (int e = threadIdx.x; e < 625; e += 800) As[e] = A[(size_t)g * 625 + e];
  __syncthreads();

  int j = threadIdx.x >> 5;
  int lane = threadIdx.x & 31;
  float av[25];
#pragma unroll
  for (int vv = 0; vv < 25; vv++) av[vv] = As[vv * 25 + j];

  const float *src = g_s1 + (size_t)g * 14400;
  float *dst = g_s2 + ((size_t)g * 25 + j) * 576;
  for (int it = 0; it < 18; it++) {
    int idx = lane + it * 32;
    float acc = 0.f;
#pragma unroll
    for (int vv = 0; vv < 25; vv++)
      acc = fmaf(av[vv], __ldg(src + vv * 576 + idx), acc);
    dst[idx] = acc;
  }
}

// ---------------------------------------------------------------------------
// K3: full epilogue via the factor trick.
//   eig(L) = (V, w)            [two-sided jacobi, 5 sweeps]
//   M = W V diag(e^{w/2})      [smem-broadcast matmul + scalar; no recompose!]
//   Z = W e^L W^T = M M^T      [never formed]
//   one-sided jacobi on M      -> columns sigma_k h_k, sigma = sqrt(eig(Z))
//   ||Z||_F = sqrt(sum sigma^4)  (normalize commutes with sqrt)
//   out = sqrt(Z/||Z||) = sum_k (sigma_k/sqrt(c)) h_k h_k^T
//       = recompose(M, 1/(sigma*sqrt(c)))   [rsqrtf(ss*c)]
// No 1/(2 sqrt(lambda)) residual amplification anywhere.
// ---------------------------------------------------------------------------
__global__ void __launch_bounds__(128) k_final(const float *__restrict__ Wm,
                                               float *__restrict__ out) {
  __shared__ float tbuf[WPB][600];
  __shared__ float Ws[576];
  for (int t = threadIdx.x; t < 576; t += 128) Ws[t] = Wm[t];
  __syncthreads();

  int wid = threadIdx.x >> 5, lane = threadIdx.x & 31;
  int mIdx = blockIdx.x * WPB + wid;

  const float *src = g_s2 + (size_t)mIdx * 576;
  float a[24];
#pragma unroll
  for (int i = 0; i < 24; i++) a[i] = (lane < 24) ? src[i * 24 + lane] : 0.f;

  // eig of aggregated log-matrix
  float v[24], w;
  jacobi24<5>(a, v, w, lane);

  // M column j = (W * v_j) * exp(w_j / 2); W broadcast from smem, no shfl.
  float es = expf(0.5f * w);
  float m[24];
#pragma unroll
  for (int i = 0; i < 24; i++) {
    float acc = 0.f;
    const float4 *wr = (const float4 *)&Ws[i * 24];
#pragma unroll
    for (int k4 = 0; k4 < 6; k4++) {
      float4 w4 = wr[k4];
      acc = fmaf(w4.x, v[k4 * 4 + 0], acc);
      acc = fmaf(w4.y, v[k4 * 4 + 1], acc);
      acc = fmaf(w4.z, v[k4 * 4 + 2], acc);
      acc = fmaf(w4.w, v[k4 * 4 + 3], acc);
    }
    m[i] = acc * es;
  }

  // One-sided Jacobi: orthogonalize columns of M (6 sweeps, cheap rounds).
  jacobi1s<6>(m, lane);

  // sigma^2 = ||column||^2 (fresh recompute); idle lanes give 0.
  float ss = 0.f;
#pragma unroll
  for (int i = 0; i < 24; i++) ss = fmaf(m[i], m[i], ss);

  // c = ||Z||_F = sqrt(sum sigma^4)
  float s4 = ss * ss;
#pragma unroll
  for (int off = 16; off > 0; off >>= 1) s4 += __shfl_xor_sync(FULL, s4, off);
  float c = sqrtf(fmaxf(s4, 1e-30f));

  // scalar per column: (sigma/sqrt(c)) / sigma^2 = 1/(sigma*sqrt(c))
  float fscl = rsqrtf(fmaxf(ss, 1e-24f) * c);

  float r[24];
  recompose24(m, fscl, r, lane, tbuf[wid]);

  float *dst = out + (size_t)mIdx * 576;
  if (lane < 24) {
#pragma unroll
    for (int i = 0; i < 24; i++) dst[i * 24 + lane] = r[i];
  }
}

// ---------------------------------------------------------------------------
extern "C" void kernel_launch(void *const *d_in, const int *in_sizes, int n_in,
                              void *d_out, int out_size) {
  const float *x = nullptr, *A = nullptr, *Wm = nullptr;
  for (int i = 0; i < n_in; i++) {
    if (in_sizes[i] == 22118400)     x  = (const float *)d_in[i];
    else if (in_sizes[i] == 960000)  A  = (const float *)d_in[i];
    else if (in_sizes[i] == 576)     Wm = (const float *)d_in[i];
  }
  float *out = (float *)d_out;

  k_logm<<<NMAT / WPB, 128>>>(x);
  k_agg<<<1536, 800>>>(A);
  k_final<<<NMAT / WPB, 128>>>(Wm, out);
}

// round 12
// speedup vs baseline: 2.0193x; 1.5116x over previous
#include <cuda_runtime.h>
#include <math.h>

#define FULL 0xffffffffu
#define NMAT 38400
#define WPB 4
#define SHIFT 4.0f

// 38400 * 576 = 22118400 floats (88.5 MB) each — allowed __device__ scratch
__device__ float g_s1[22118400];
__device__ float g_s2[22118400];

// ---------------------------------------------------------------------------
// Warp-parallel Cholesky of SPD 24x24, lane j holds column j (full symmetric
// storage in). Out: x = column j of lower-triangular C (X = C C^T), strict
// upper zeroed. Right-looking; the trailing submatrix stays SYMMETRIC, so the
// multiplier l[j,k] is element k of lane j's OWN column — compile-time index,
// no smem, no dynamic register indexing. ~25 shfl/round, 24 rounds.
// Idle lanes (>=24) carry zeros and stay zero (sel = 0*rd = 0).
// ---------------------------------------------------------------------------
__device__ __forceinline__ void chol24(float (&x)[24], int lane) {
#pragma unroll
  for (int k = 0; k < 24; k++) {
    float dk = __shfl_sync(FULL, x[k], k);   // pivot
    float rd = rsqrtf(dk);
    float ljk = x[k] * rd;                   // l[j,k] for lanes j>k (own elem k)
    float sel = (lane > k) ? ljk : 0.f;
    bool  isk = (lane == k);
#pragma unroll
    for (int i = k; i < 24; i++) {
      float lki = __shfl_sync(FULL, x[i], k) * rd;   // l[i,k] broadcast
      x[i] = isk ? lki : fmaf(-sel, lki, x[i]);      // finalize col k / update
    }
  }
#pragma unroll
  for (int i = 0; i < 24; i++)
    if (i < lane) x[i] = 0.f;                // strict upper of own column
}

// ---------------------------------------------------------------------------
// One-sided Jacobi column orthogonalization of a 24x24 factor M (lane j =
// column j in b[24]). Implicitly diagonalizes M^T M; on exit column j =
// sigma_k * u_k with M M^T = sum sigma^2 u u^T. sigma^2 = ||col||^2, so any
// spectral function of M M^T is recompose(b, f(ss)/ss) — no sqrt/eig residual
// amplification. Valid ONLY on explicit factors (R8 lesson: applying this to
// a symmetric matrix itself squares the condition number via Gram = A^2).
// No V accumulation, no row update, no select-chain: ~115 instr/round.
// ---------------------------------------------------------------------------
template <int NS>
__device__ __forceinline__ void jacobi1s(float (&b)[24], int lane) {
  float app = 0.f;
#pragma unroll
  for (int i = 0; i < 24; i++) app = fmaf(b[i], b[i], app);

  for (int sweep = 0; sweep < NS; sweep++) {
#pragma unroll
    for (int r = 0; r < 23; r++) {
      int partner;
      if (lane >= 24)      partner = lane;
      else if (lane == 23) partner = r;
      else if (lane == r)  partner = 23;
      else                 partner = (2 * r + 23 - lane) % 23;

      float bp[24];
      float d0 = 0.f, d1 = 0.f, d2 = 0.f;
#pragma unroll
      for (int i = 0; i < 24; i += 3) {
        bp[i]     = __shfl_sync(FULL, b[i],     partner);
        d0 = fmaf(b[i],     bp[i],     d0);
        bp[i + 1] = __shfl_sync(FULL, b[i + 1], partner);
        d1 = fmaf(b[i + 1], bp[i + 1], d1);
        bp[i + 2] = __shfl_sync(FULL, b[i + 2], partner);
        d2 = fmaf(b[i + 2], bp[i + 2], d2);
      }
      float apq = (d0 + d1) + d2;           // identical on both pair lanes
      float nq  = __shfl_sync(FULL, app, partner);
      bool  isLow = lane <= partner;
      float nlow  = isLow ? app : nq;
      float nhigh = isLow ? nq : app;

      float c, s, tt;
      if (fabsf(apq) > 1e-30f) {
        float tau = (nhigh - nlow) / (2.0f * apq);
        tt = ((tau >= 0.f) ? 1.f : -1.f) /
             (fabsf(tau) + sqrtf(fmaf(tau, tau, 1.f)));
        c = rsqrtf(fmaf(tt, tt, 1.f));
        s = tt * c;
      } else { c = 1.f; s = 0.f; tt = 0.f; }

      float tse = isLow ? -tt : tt;
      app = fmaf(tse, apq, app);            // norm^2 update (exact Jacobi law)
      float se = isLow ? -s : s;
#pragma unroll
      for (int i = 0; i < 24; i++)
        b[i] = fmaf(se, bp[i], c * b[i]);   // own-column rotation only
    }
  }
}

// ---------------------------------------------------------------------------
// R = sum_k f_k col_k col_k^T. u = columns (lane j holds col j), f per-lane.
// Non-destructive; tb = per-warp smem scratch (>= 600 floats).
// ---------------------------------------------------------------------------
__device__ __forceinline__ void recompose24(const float (&u)[24], float f,
                                            float (&r)[24], int lane, float *tb) {
  __syncwarp();
  if (lane < 24) {
#pragma unroll
    for (int i = 0; i < 24; i++) tb[lane * 25 + i] = u[i];
  }
  __syncwarp();
  float ut[24];
  int ln = (lane < 24) ? lane : 0;
#pragma unroll
  for (int i = 0; i < 24; i++) ut[i] = tb[i * 25 + ln];

  float m[24];
#pragma unroll
  for (int i = 0; i < 24; i++) { m[i] = u[i] * f; r[i] = 0.f; }
#pragma unroll
  for (int k = 0; k < 24; k++) {
    float coef = ut[k];
#pragma unroll
    for (int i = 0; i < 24; i++)
      r[i] = fmaf(__shfl_sync(FULL, m[i], k), coef, r[i]);
  }
  __syncwarp();
}

// ---------------------------------------------------------------------------
// K1: x -> sym_logm(x) via Cholesky + one-sided Jacobi.
// x = C C^T (SPD, >= 0.5 I); one-sided on C gives sigma^2 = eig(x) = ss,
// logm(x) = recompose(cols, log(ss)/ss). One warp per matrix.
// ---------------------------------------------------------------------------
__global__ void __launch_bounds__(128) k_logm(const float *__restrict__ x) {
  __shared__ float tbuf[WPB][600];
  int wid = threadIdx.x >> 5, lane = threadIdx.x & 31;
  int m = blockIdx.x * WPB + wid;
  const float *src = x + (size_t)m * 576;

  float a[24];
#pragma unroll
  for (int i = 0; i < 24; i++) a[i] = (lane < 24) ? src[i * 24 + lane] : 0.f;

  chol24(a, lane);
  jacobi1s<6>(a, lane);

  float ss = 0.f;
#pragma unroll
  for (int i = 0; i < 24; i++) ss = fmaf(a[i], a[i], ss);
  ss = fmaxf(ss, 1e-24f);
  float f = logf(ss) / ss;           // log(lambda)/lambda, lambda = ss

  float r[24];
  recompose24(a, f, r, lane, tbuf[wid]);

  float *dst = g_s1 + (size_t)m * 576;
  if (lane < 24) {
#pragma unroll
    for (int i = 0; i < 24; i++) dst[i * 24 + lane] = r[i];
  }
}

// ---------------------------------------------------------------------------
// K2: tangent-space aggregation.
// ---------------------------------------------------------------------------
__global__ void __launch_bounds__(800) k_agg(const float *__restrict__ A) {
  __shared__ float As[625];
  int g = blockIdx.x;
  for (int e = threadIdx.x; e < 625; e += 800) As[e] = A[(size_t)g * 625 + e];
  __syncthreads();

  int j = threadIdx.x >> 5;
  int lane = threadIdx.x & 31;
  float av[25];
#pragma unroll
  for (int vv = 0; vv < 25; vv++) av[vv] = As[vv * 25 + j];

  const float *src = g_s1 + (size_t)g * 14400;
  float *dst = g_s2 + ((size_t)g * 25 + j) * 576;
  for (int it = 0; it < 18; it++) {
    int idx = lane + it * 32;
    float acc = 0.f;
#pragma unroll
    for (int vv = 0; vv < 25; vv++)
      acc = fmaf(av[vv], __ldg(src + vv * 576 + idx), acc);
    dst[idx] = acc;
  }
}

// ---------------------------------------------------------------------------
// K3: epilogue, fully factor-based (no two-sided Jacobi anywhere):
//   stage A: L+SHIFT*I = C C^T (SPD, spectrum ~[3.3,5.8], cond<2);
//            one-sided on C -> cols sigma_k u_k, lambda = ss - SHIFT.
//            M col = (W col) * e^{lambda/2}/sigma  (unit u folded via 1/sigma)
//   stage B: Z = W e^L W^T = M M^T (never formed); one-sided on M ->
//            sigma'^2 = eig(Z); ||Z||_F = sqrt(sum sigma'^4);
//            out = sqrt(Z/||Z||) = recompose(M', rsqrt(ss' * c)).
// ---------------------------------------------------------------------------
__global__ void __launch_bounds__(128) k_final(const float *__restrict__ Wm,
                                               float *__restrict__ out) {
  __shared__ float tbuf[WPB][600];
  __shared__ float Ws[576];
  for (int t = threadIdx.x; t < 576; t += 128) Ws[t] = Wm[t];
  __syncthreads();

  int wid = threadIdx.x >> 5, lane = threadIdx.x & 31;
  int mIdx = blockIdx.x * WPB + wid;

  const float *src = g_s2 + (size_t)mIdx * 576;
  float a[24];
#pragma unroll
  for (int i = 0; i < 24; i++)
    a[i] = (lane < 24) ? (src[i * 24 + lane] + ((i == lane) ? SHIFT : 0.f))
                       : 0.f;

  // stage A: shifted Cholesky + one-sided Jacobi
  chol24(a, lane);
  jacobi1s<6>(a, lane);

  float ss = 0.f;
#pragma unroll
  for (int i = 0; i < 24; i++) ss = fmaf(a[i], a[i], ss);
  float ssg = fmaxf(ss, 1e-24f);
  float lam = ss - SHIFT;                    // eigenvalue of L
  float scl = expf(0.5f * lam) * rsqrtf(ssg);  // e^{lam/2} / sigma

  // M column j = (W * col_j) * scl ; W broadcast from smem, no shuffles.
  float m[24];
#pragma unroll
  for (int i = 0; i < 24; i++) {
    float acc = 0.f;
    const float4 *wr = (const float4 *)&Ws[i * 24];
#pragma unroll
    for (int k4 = 0; k4 < 6; k4++) {
      float4 w4 = wr[k4];
      acc = fmaf(w4.x, a[k4 * 4 + 0], acc);
      acc = fmaf(w4.y, a[k4 * 4 + 1], acc);
      acc = fmaf(w4.z, a[k4 * 4 + 2], acc);
      acc = fmaf(w4.w, a[k4 * 4 + 3], acc);
    }
    m[i] = acc * scl;
  }

  // stage B: one-sided Jacobi on M
  jacobi1s<6>(m, lane);

  float ss2 = 0.f;
#pragma unroll
  for (int i = 0; i < 24; i++) ss2 = fmaf(m[i], m[i], ss2);

  // c = ||Z||_F = sqrt(sum sigma^4)
  float s4 = ss2 * ss2;
#pragma unroll
  for (int off = 16; off > 0; off >>= 1) s4 += __shfl_xor_sync(FULL, s4, off);
  float c = sqrtf(fmaxf(s4, 1e-30f));

  // per-column scalar: (sigma/sqrt(c))/sigma^2 = 1/(sigma*sqrt(c))
  float fscl = rsqrtf(fmaxf(ss2, 1e-24f) * c);

  float r[24];
  recompose24(m, fscl, r, lane, tbuf[wid]);

  float *dst = out + (size_t)mIdx * 576;
  if (lane < 24) {
#pragma unroll
    for (int i = 0; i < 24; i++) dst[i * 24 + lane] = r[i];
  }
}

// ---------------------------------------------------------------------------
extern "C" void kernel_launch(void *const *d_in, const int *in_sizes, int n_in,
                              void *d_out, int out_size) {
  const float *x = nullptr, *A = nullptr, *Wm = nullptr;
  for (int i = 0; i < n_in; i++) {
    if (in_sizes[i] == 22118400)     x  = (const float *)d_in[i];
    else if (in_sizes[i] == 960000)  A  = (const float *)d_in[i];
    else if (in_sizes[i] == 576)     Wm = (const float *)d_in[i];
  }
  float *out = (float *)d_out;

  k_logm<<<NMAT / WPB, 128>>>(x);
  k_agg<<<1536, 800>>>(A);
  k_final<<<NMAT / WPB, 128>>>(Wm, out);
}

// round 13
// speedup vs baseline: 2.3363x; 1.1570x over previous
#include <cuda_runtime.h>
#include <math.h>

#define FULL 0xffffffffu
#define NMAT 38400
#define WPB 4
#define SHIFT 4.0f

// 38400 * 576 = 22118400 floats (88.5 MB) each — allowed __device__ scratch
__device__ float g_s1[22118400];
__device__ float g_s2[22118400];

// ---------------------------------------------------------------------------
// Warp-parallel Cholesky of SPD 24x24, lane j holds column j (full symmetric
// storage in). Out: x = column j of lower-triangular C (X = C C^T), strict
// upper zeroed. Right-looking; the trailing submatrix stays SYMMETRIC, so the
// multiplier l[j,k] is element k of lane j's OWN column — compile-time index,
// no smem, no dynamic register indexing. ~25 shfl/round, 24 rounds.
// Idle lanes (>=24) carry zeros and stay zero (sel = 0*rd = 0).
// ---------------------------------------------------------------------------
__device__ __forceinline__ void chol24(float (&x)[24], int lane) {
#pragma unroll
  for (int k = 0; k < 24; k++) {
    float dk = __shfl_sync(FULL, x[k], k);   // pivot
    float rd = rsqrtf(dk);
    float ljk = x[k] * rd;                   // l[j,k] for lanes j>k (own elem k)
    float sel = (lane > k) ? ljk : 0.f;
    bool  isk = (lane == k);
#pragma unroll
    for (int i = k; i < 24; i++) {
      float lki = __shfl_sync(FULL, x[i], k) * rd;   // l[i,k] broadcast
      x[i] = isk ? lki : fmaf(-sel, lki, x[i]);      // finalize col k / update
    }
  }
#pragma unroll
  for (int i = 0; i < 24; i++)
    if (i < lane) x[i] = 0.f;                // strict upper of own column
}

// ---------------------------------------------------------------------------
// One-sided Jacobi column orthogonalization of a 24x24 factor M (lane j =
// column j in b[24]). Implicitly diagonalizes M^T M; on exit column j =
// sigma_k * u_k with M M^T = sum sigma^2 u u^T. sigma^2 = ||col||^2, so any
// spectral function of M M^T is recompose(b, f(ss)/ss) — no sqrt/eig residual
// amplification. Valid ONLY on explicit factors (R8 lesson: applying this to
// a symmetric matrix itself squares the condition number via Gram = A^2).
// No V accumulation, no row update, no select-chain: ~115 instr/round.
// ---------------------------------------------------------------------------
template <int NS>
__device__ __forceinline__ void jacobi1s(float (&b)[24], int lane) {
  float app = 0.f;
#pragma unroll
  for (int i = 0; i < 24; i++) app = fmaf(b[i], b[i], app);

  for (int sweep = 0; sweep < NS; sweep++) {
#pragma unroll
    for (int r = 0; r < 23; r++) {
      int partner;
      if (lane >= 24)      partner = lane;
      else if (lane == 23) partner = r;
      else if (lane == r)  partner = 23;
      else                 partner = (2 * r + 23 - lane) % 23;

      float bp[24];
      float d0 = 0.f, d1 = 0.f, d2 = 0.f;
#pragma unroll
      for (int i = 0; i < 24; i += 3) {
        bp[i]     = __shfl_sync(FULL, b[i],     partner);
        d0 = fmaf(b[i],     bp[i],     d0);
        bp[i + 1] = __shfl_sync(FULL, b[i + 1], partner);
        d1 = fmaf(b[i + 1], bp[i + 1], d1);
        bp[i + 2] = __shfl_sync(FULL, b[i + 2], partner);
        d2 = fmaf(b[i + 2], bp[i + 2], d2);
      }
      float apq = (d0 + d1) + d2;           // identical on both pair lanes
      float nq  = __shfl_sync(FULL, app, partner);
      bool  isLow = lane <= partner;
      float nlow  = isLow ? app : nq;
      float nhigh = isLow ? nq : app;

      float c, s, tt;
      if (fabsf(apq) > 1e-30f) {
        float tau = (nhigh - nlow) / (2.0f * apq);
        tt = ((tau >= 0.f) ? 1.f : -1.f) /
             (fabsf(tau) + sqrtf(fmaf(tau, tau, 1.f)));
        c = rsqrtf(fmaf(tt, tt, 1.f));
        s = tt * c;
      } else { c = 1.f; s = 0.f; tt = 0.f; }

      float tse = isLow ? -tt : tt;
      app = fmaf(tse, apq, app);            // norm^2 update (exact Jacobi law)
      float se = isLow ? -s : s;
#pragma unroll
      for (int i = 0; i < 24; i++)
        b[i] = fmaf(se, bp[i], c * b[i]);   // own-column rotation only
    }
  }
}

// ---------------------------------------------------------------------------
// R = sum_k f_k col_k col_k^T. u = columns (lane j holds col j), f per-lane.
// Non-destructive; tb = per-warp smem scratch (>= 600 floats).
// ---------------------------------------------------------------------------
__device__ __forceinline__ void recompose24(const float (&u)[24], float f,
                                            float (&r)[24], int lane, float *tb) {
  __syncwarp();
  if (lane < 24) {
#pragma unroll
    for (int i = 0; i < 24; i++) tb[lane * 25 + i] = u[i];
  }
  __syncwarp();
  float ut[24];
  int ln = (lane < 24) ? lane : 0;
#pragma unroll
  for (int i = 0; i < 24; i++) ut[i] = tb[i * 25 + ln];

  float m[24];
#pragma unroll
  for (int i = 0; i < 24; i++) { m[i] = u[i] * f; r[i] = 0.f; }
#pragma unroll
  for (int k = 0; k < 24; k++) {
    float coef = ut[k];
#pragma unroll
    for (int i = 0; i < 24; i++)
      r[i] = fmaf(__shfl_sync(FULL, m[i], k), coef, r[i]);
  }
  __syncwarp();
}

// ---------------------------------------------------------------------------
// K1: x -> sym_logm(x) via Cholesky + one-sided Jacobi.
// x = C C^T (SPD, >= 0.5 I, cond ~ 12); 5 sweeps (quadratic regime, and no
// downstream residual amplification in the factor pipeline).
// ---------------------------------------------------------------------------
__global__ void __launch_bounds__(128) k_logm(const float *__restrict__ x) {
  __shared__ float tbuf[WPB][600];
  int wid = threadIdx.x >> 5, lane = threadIdx.x & 31;
  int m = blockIdx.x * WPB + wid;
  const float *src = x + (size_t)m * 576;

  float a[24];
#pragma unroll
  for (int i = 0; i < 24; i++) a[i] = (lane < 24) ? src[i * 24 + lane] : 0.f;

  chol24(a, lane);
  jacobi1s<5>(a, lane);

  float ss = 0.f;
#pragma unroll
  for (int i = 0; i < 24; i++) ss = fmaf(a[i], a[i], ss);
  ss = fmaxf(ss, 1e-24f);
  float f = logf(ss) / ss;           // log(lambda)/lambda, lambda = ss

  float r[24];
  recompose24(a, f, r, lane, tbuf[wid]);

  float *dst = g_s1 + (size_t)m * 576;
  if (lane < 24) {
#pragma unroll
    for (int i = 0; i < 24; i++) dst[i * 24 + lane] = r[i];
  }
}

// ---------------------------------------------------------------------------
// K2: tangent-space aggregation.
// ---------------------------------------------------------------------------
__global__ void __launch_bounds__(800) k_agg(const float *__restrict__ A) {
  __shared__ float As[625];
  int g = blockIdx.x;
  for (int e = threadIdx.x; e < 625; e += 800) As[e] = A[(size_t)g * 625 + e];
  __syncthreads();

  int j = threadIdx.x >> 5;
  int lane = threadIdx.x & 31;
  float av[25];
#pragma unroll
  for (int vv = 0; vv < 25; vv++) av[vv] = As[vv * 25 + j];

  const float *src = g_s1 + (size_t)g * 14400;
  float *dst = g_s2 + ((size_t)g * 25 + j) * 576;
  for (int it = 0; it < 18; it++) {
    int idx = lane + it * 32;
    float acc = 0.f;
#pragma unroll
    for (int vv = 0; vv < 25; vv++)
      acc = fmaf(av[vv], __ldg(src + vv * 576 + idx), acc);
    dst[idx] = acc;
  }
}

// ---------------------------------------------------------------------------
// K3: epilogue, fully factor-based:
//   stage A: L+SHIFT*I = C C^T (SPD, spectrum ~[3.3,5.8], COND < 2 ->
//            4 sweeps suffice); cols sigma_k u_k, lambda = ss - SHIFT.
//            M col = (W col) * e^{lambda/2}/sigma.
//   stage B: Z = W e^L W^T = M M^T (never formed); one-sided on M (6 sweeps,
//            widest spectrum, sets final accuracy) -> sigma'^2 = eig(Z);
//            ||Z||_F = sqrt(sum sigma'^4);
//            out = sqrt(Z/||Z||) = recompose(M', rsqrt(ss' * c)).
// ---------------------------------------------------------------------------
__global__ void __launch_bounds__(128) k_final(const float *__restrict__ Wm,
                                               float *__restrict__ out) {
  __shared__ float tbuf[WPB][600];
  __shared__ float Ws[576];
  for (int t = threadIdx.x; t < 576; t += 128) Ws[t] = Wm[t];
  __syncthreads();

  int wid = threadIdx.x >> 5, lane = threadIdx.x & 31;
  int mIdx = blockIdx.x * WPB + wid;

  const float *src = g_s2 + (size_t)mIdx * 576;
  float a[24];
#pragma unroll
  for (int i = 0; i < 24; i++)
    a[i] = (lane < 24) ? (src[i * 24 + lane] + ((i == lane) ? SHIFT : 0.f))
                       : 0.f;

  // stage A: shifted Cholesky + one-sided Jacobi (cond<2 -> 4 sweeps)
  chol24(a, lane);
  jacobi1s<4>(a, lane);

  float ss = 0.f;
#pragma unroll
  for (int i = 0; i < 24; i++) ss = fmaf(a[i], a[i], ss);
  float ssg = fmaxf(ss, 1e-24f);
  float lam = ss - SHIFT;                    // eigenvalue of L
  float scl = expf(0.5f * lam) * rsqrtf(ssg);  // e^{lam/2} / sigma

  // M column j = (W * col_j) * scl ; W broadcast from smem, no shuffles.
  float m[24];
#pragma unroll
  for (int i = 0; i < 24; i++) {
    float acc = 0.f;
    const float4 *wr = (const float4 *)&Ws[i * 24];
#pragma unroll
    for (int k4 = 0; k4 < 6; k4++) {
      float4 w4 = wr[k4];
      acc = fmaf(w4.x, a[k4 * 4 + 0], acc);
      acc = fmaf(w4.y, a[k4 * 4 + 1], acc);
      acc = fmaf(w4.z, a[k4 * 4 + 2], acc);
      acc = fmaf(w4.w, a[k4 * 4 + 3], acc);
    }
    m[i] = acc * scl;
  }

  // stage B: one-sided Jacobi on M (accuracy-critical: keep 6 sweeps)
  jacobi1s<6>(m, lane);

  float ss2 = 0.f;
#pragma unroll
  for (int i = 0; i < 24; i++) ss2 = fmaf(m[i], m[i], ss2);

  // c = ||Z||_F = sqrt(sum sigma^4)
  float s4 = ss2 * ss2;
#pragma unroll
  for (int off = 16; off > 0; off >>= 1) s4 += __shfl_xor_sync(FULL, s4, off);
  float c = sqrtf(fmaxf(s4, 1e-30f));

  // per-column scalar: (sigma/sqrt(c))/sigma^2 = 1/(sigma*sqrt(c))
  float fscl = rsqrtf(fmaxf(ss2, 1e-24f) * c);

  float r[24];
  recompose24(m, fscl, r, lane, tbuf[wid]);

  float *dst = out + (size_t)mIdx * 576;
  if (lane < 24) {
#pragma unroll
    for (int i = 0; i < 24; i++) dst[i * 24 + lane] = r[i];
  }
}

// ---------------------------------------------------------------------------
extern "C" void kernel_launch(void *const *d_in, const int *in_sizes, int n_in,
                              void *d_out, int out_size) {
  const float *x = nullptr, *A = nullptr, *Wm = nullptr;
  for (int i = 0; i < n_in; i++) {
    if (in_sizes[i] == 22118400)     x  = (const float *)d_in[i];
    else if (in_sizes[i] == 960000)  A  = (const float *)d_in[i];
    else if (in_sizes[i] == 576)     Wm = (const float *)d_in[i];
  }
  float *out = (float *)d_out;

  k_logm<<<NMAT / WPB, 128>>>(x);
  k_agg<<<1536, 800>>>(A);
  k_final<<<NMAT / WPB, 128>>>(Wm, out);
}

// round 14
// speedup vs baseline: 2.5530x; 1.0927x over previous
#include <cuda_runtime.h>
#include <math.h>

#define FULL 0xffffffffu
#define NMAT 38400
#define WPB 4
#define SHIFT 4.0f

typedef unsigned long long u64;

// 38400 * 576 = 22118400 floats (88.5 MB) each — allowed __device__ scratch
__device__ float g_s1[22118400];
__device__ float g_s2[22118400];

// ---------------- packed f32x2 helpers (Blackwell sm_103a) -----------------
__device__ __forceinline__ u64 pk2(float a, float b) {
  u64 r; asm("mov.b64 %0, {%1, %2};" : "=l"(r) : "f"(a), "f"(b)); return r;
}
__device__ __forceinline__ void upk2(u64 v, float &a, float &b) {
  asm("mov.b64 {%0, %1}, %2;" : "=f"(a), "=f"(b) : "l"(v));
}
__device__ __forceinline__ u64 fma2(u64 a, u64 b, u64 c) {
  u64 d; asm("fma.rn.f32x2 %0, %1, %2, %3;" : "=l"(d) : "l"(a), "l"(b), "l"(c));
  return d;
}
__device__ __forceinline__ u64 mul2(u64 a, u64 b) {
  u64 d; asm("mul.rn.f32x2 %0, %1, %2;" : "=l"(d) : "l"(a), "l"(b)); return d;
}
__device__ __forceinline__ u64 add2(u64 a, u64 b) {
  u64 d; asm("add.rn.f32x2 %0, %1, %2;" : "=l"(d) : "l"(a), "l"(b)); return d;
}
__device__ __forceinline__ float hsum2(u64 v) {
  float a, b; upk2(v, a, b); return a + b;
}

// ---------------------------------------------------------------------------
// Warp-parallel Cholesky of SPD 24x24, packed: lane j holds column j as 12
// f32x2 words (elements 2t, 2t+1). Right-looking; multiplier l[j,k] is a
// compile-time-indexed element of the lane's OWN column. The j-loop starts at
// k/2 — elements below that land in the i<lane junk region zeroed at the end.
// Idle lanes (>=24) carry zeros and stay zero.
// ---------------------------------------------------------------------------
__device__ __forceinline__ void chol24_2(u64 (&x)[12], int lane) {
#pragma unroll
  for (int k = 0; k < 24; k++) {
    u64 pv = __shfl_sync(FULL, x[k >> 1], k);      // pivot word
    float p0, p1; upk2(pv, p0, p1);
    float dk = (k & 1) ? p1 : p0;
    float rd = rsqrtf(dk);
    float q0, q1; upk2(x[k >> 1], q0, q1);
    float ljk = ((k & 1) ? q1 : q0) * rd;          // own element k
    float sel = (lane > k) ? -ljk : 0.f;
    u64 sel2 = pk2(sel, sel);
    u64 rd2  = pk2(rd, rd);
    bool isk = (lane == k);
#pragma unroll
    for (int j = k >> 1; j < 12; j++) {
      u64 lki = mul2(__shfl_sync(FULL, x[j], k), rd2);
      u64 upd = fma2(sel2, lki, x[j]);
      x[j] = isk ? lki : upd;
    }
  }
  // zero elements i < lane of own column (strict upper + update junk)
#pragma unroll
  for (int j = 0; j < 12; j++) {
    float z0, z1; upk2(x[j], z0, z1);
    if (2 * j     < lane) z0 = 0.f;
    if (2 * j + 1 < lane) z1 = 0.f;
    x[j] = pk2(z0, z1);
  }
}

// ---------------------------------------------------------------------------
// One-sided Jacobi column orthogonalization of a 24x24 factor, packed.
// Lane j = column j as 12 f32x2 words. Implicit Gram = M^T M; sigma^2 =
// ||col||^2; spectral f of M M^T = recompose(cols, f(ss)/ss). Valid only on
// explicit factors (R8 lesson: on a symmetric matrix it squares cond).
// apq identical on both pair lanes: elementwise products commute, packed
// accumulation order identical. c,s scalar per lane, broadcast into f32x2.
// ---------------------------------------------------------------------------
template <int NS>
__device__ __forceinline__ void jacobi1s2(u64 (&b)[12], int lane) {
  float app;
  {
    u64 a0 = 0ULL, a1 = 0ULL;
#pragma unroll
    for (int j = 0; j < 12; j += 2) {
      a0 = fma2(b[j], b[j], a0);
      a1 = fma2(b[j + 1], b[j + 1], a1);
    }
    app = hsum2(add2(a0, a1));
  }

  for (int sweep = 0; sweep < NS; sweep++) {
#pragma unroll
    for (int r = 0; r < 23; r++) {
      int partner;
      if (lane >= 24)      partner = lane;
      else if (lane == 23) partner = r;
      else if (lane == r)  partner = 23;
      else                 partner = (2 * r + 23 - lane) % 23;

      u64 bp[12];
      u64 d0 = 0ULL, d1 = 0ULL;
#pragma unroll
      for (int j = 0; j < 12; j += 2) {
        bp[j] = __shfl_sync(FULL, b[j], partner);
        d0 = fma2(b[j], bp[j], d0);
        bp[j + 1] = __shfl_sync(FULL, b[j + 1], partner);
        d1 = fma2(b[j + 1], bp[j + 1], d1);
      }
      float apq = hsum2(add2(d0, d1));     // identical on both pair lanes
      float nq  = __shfl_sync(FULL, app, partner);
      bool  isLow = lane <= partner;
      float nlow  = isLow ? app : nq;
      float nhigh = isLow ? nq : app;

      float c, s, tt;
      if (fabsf(apq) > 1e-30f) {
        float tau = (nhigh - nlow) / (2.0f * apq);
        tt = ((tau >= 0.f) ? 1.f : -1.f) /
             (fabsf(tau) + sqrtf(fmaf(tau, tau, 1.f)));
        c = rsqrtf(fmaf(tt, tt, 1.f));
        s = tt * c;
      } else { c = 1.f; s = 0.f; tt = 0.f; }

      float tse = isLow ? -tt : tt;
      app = fmaf(tse, apq, app);           // norm^2 update (exact Jacobi law)
      float se = isLow ? -s : s;
      u64 c2  = pk2(c, c);
      u64 se2 = pk2(se, se);
#pragma unroll
      for (int j = 0; j < 12; j++)
        b[j] = fma2(se2, bp[j], mul2(c2, b[j]));   // packed column rotation
    }
  }
}

// ---------------------------------------------------------------------------
// R = sum_k f_k col_k col_k^T, packed. u = columns (12 f32x2 per lane),
// f per-lane scalar. tb = per-warp smem scratch (>= 600 floats).
// ---------------------------------------------------------------------------
__device__ __forceinline__ void recompose24_2(const u64 (&u)[12], float f,
                                              u64 (&r)[12], int lane,
                                              float *tb) {
  __syncwarp();
  if (lane < 24) {
#pragma unroll
    for (int j = 0; j < 12; j++) {
      float a, b; upk2(u[j], a, b);
      tb[lane * 25 + 2 * j]     = a;
      tb[lane * 25 + 2 * j + 1] = b;
    }
  }
  __syncwarp();
  float ut[24];
  int ln = (lane < 24) ? lane : 0;
#pragma unroll
  for (int i = 0; i < 24; i++) ut[i] = tb[i * 25 + ln];

  u64 f2 = pk2(f, f);
  u64 m[12];
#pragma unroll
  for (int j = 0; j < 12; j++) { m[j] = mul2(u[j], f2); r[j] = 0ULL; }
#pragma unroll
  for (int k = 0; k < 24; k++) {
    u64 c2 = pk2(ut[k], ut[k]);
#pragma unroll
    for (int j = 0; j < 12; j++)
      r[j] = fma2(__shfl_sync(FULL, m[j], k), c2, r[j]);
  }
  __syncwarp();
}

// packed ||col||^2
__device__ __forceinline__ float colnorm2(const u64 (&b)[12]) {
  u64 a0 = 0ULL, a1 = 0ULL;
#pragma unroll
  for (int j = 0; j < 12; j += 2) {
    a0 = fma2(b[j], b[j], a0);
    a1 = fma2(b[j + 1], b[j + 1], a1);
  }
  return hsum2(add2(a0, a1));
}

// ---------------------------------------------------------------------------
// K1: x -> sym_logm(x) via Cholesky + packed one-sided Jacobi. 5 sweeps.
// ---------------------------------------------------------------------------
__global__ void __launch_bounds__(128) k_logm(const float *__restrict__ x) {
  __shared__ float tbuf[WPB][600];
  int wid = threadIdx.x >> 5, lane = threadIdx.x & 31;
  int m = blockIdx.x * WPB + wid;
  const float *src = x + (size_t)m * 576;

  u64 a[12];
#pragma unroll
  for (int j = 0; j < 12; j++) {
    float e0 = (lane < 24) ? src[(2 * j) * 24 + lane] : 0.f;
    float e1 = (lane < 24) ? src[(2 * j + 1) * 24 + lane] : 0.f;
    a[j] = pk2(e0, e1);
  }

  chol24_2(a, lane);
  jacobi1s2<5>(a, lane);

  float ss = fmaxf(colnorm2(a), 1e-24f);
  float f = logf(ss) / ss;               // log(lambda)/lambda, lambda = ss

  u64 r[12];
  recompose24_2(a, f, r, lane, tbuf[wid]);

  float *dst = g_s1 + (size_t)m * 576;
  if (lane < 24) {
#pragma unroll
    for (int j = 0; j < 12; j++) {
      float e0, e1; upk2(r[j], e0, e1);
      dst[(2 * j) * 24 + lane]     = e0;
      dst[(2 * j + 1) * 24 + lane] = e1;
    }
  }
}

// ---------------------------------------------------------------------------
// K2: tangent-space aggregation (unchanged).
// ---------------------------------------------------------------------------
__global__ void __launch_bounds__(800) k_agg(const float *__restrict__ A) {
  __shared__ float As[625];
  int g = blockIdx.x;
  for (int e = threadIdx.x; e < 625; e += 800) As[e] = A[(size_t)g * 625 + e];
  __syncthreads();

  int j = threadIdx.x >> 5;
  int lane = threadIdx.x & 31;
  float av[25];
#pragma unroll
  for (int vv = 0; vv < 25; vv++) av[vv] = As[vv * 25 + j];

  const float *src = g_s1 + (size_t)g * 14400;
  float *dst = g_s2 + ((size_t)g * 25 + j) * 576;
  for (int it = 0; it < 18; it++) {
    int idx = lane + it * 32;
    float acc = 0.f;
#pragma unroll
    for (int vv = 0; vv < 25; vv++)
      acc = fmaf(av[vv], __ldg(src + vv * 576 + idx), acc);
    dst[idx] = acc;
  }
}

// ---------------------------------------------------------------------------
// K3: factor-based epilogue (packed):
//   stage A: L+SHIFT*I = C C^T (cond<2 -> 4 sweeps); lambda = ss - SHIFT;
//            M col = (W col) * e^{lambda/2}/sigma (scalar matmul, W in smem).
//   stage B: Z = M M^T (never formed); packed one-sided (6 sweeps) ->
//            sigma'^2 = eig(Z); ||Z||_F = sqrt(sum sigma'^4);
//            out = sqrt(Z/||Z||) = recompose(M', rsqrt(ss' * c)).
// ---------------------------------------------------------------------------
__global__ void __launch_bounds__(128) k_final(const float *__restrict__ Wm,
                                               float *__restrict__ out) {
  __shared__ float tbuf[WPB][600];
  __shared__ float Ws[576];
  for (int t = threadIdx.x; t < 576; t += 128) Ws[t] = Wm[t];
  __syncthreads();

  int wid = threadIdx.x >> 5, lane = threadIdx.x & 31;
  int mIdx = blockIdx.x * WPB + wid;

  const float *src = g_s2 + (size_t)mIdx * 576;
  u64 a[12];
#pragma unroll
  for (int j = 0; j < 12; j++) {
    float e0 = (lane < 24) ? src[(2 * j) * 24 + lane] : 0.f;
    float e1 = (lane < 24) ? src[(2 * j + 1) * 24 + lane] : 0.f;
    if (2 * j == lane)     e0 += SHIFT;    // diagonal shift
    if (2 * j + 1 == lane) e1 += SHIFT;
    a[j] = pk2(e0, e1);
  }

  // stage A: shifted Cholesky + one-sided Jacobi (cond<2 -> 4 sweeps)
  chol24_2(a, lane);
  jacobi1s2<4>(a, lane);

  float ss = colnorm2(a);
  float ssg = fmaxf(ss, 1e-24f);
  float lam = ss - SHIFT;                      // eigenvalue of L
  float scl = expf(0.5f * lam) * rsqrtf(ssg);  // e^{lam/2} / sigma

  // M column j = (W * col_j) * scl ; W broadcast from smem, no shuffles.
  float v[24];
#pragma unroll
  for (int j = 0; j < 12; j++) upk2(a[j], v[2 * j], v[2 * j + 1]);

  u64 mm[12];
  u64 scl2 = pk2(scl, scl);
#pragma unroll
  for (int j = 0; j < 12; j++) {
    float acc0 = 0.f, acc1 = 0.f;
    const float4 *w0 = (const float4 *)&Ws[(2 * j) * 24];
    const float4 *w1 = (const float4 *)&Ws[(2 * j + 1) * 24];
#pragma unroll
    for (int k4 = 0; k4 < 6; k4++) {
      float4 wa = w0[k4], wb = w1[k4];
      acc0 = fmaf(wa.x, v[k4 * 4 + 0], acc0);
      acc0 = fmaf(wa.y, v[k4 * 4 + 1], acc0);
      acc0 = fmaf(wa.z, v[k4 * 4 + 2], acc0);
      acc0 = fmaf(wa.w, v[k4 * 4 + 3], acc0);
      acc1 = fmaf(wb.x, v[k4 * 4 + 0], acc1);
      acc1 = fmaf(wb.y, v[k4 * 4 + 1], acc1);
      acc1 = fmaf(wb.z, v[k4 * 4 + 2], acc1);
      acc1 = fmaf(wb.w, v[k4 * 4 + 3], acc1);
    }
    mm[j] = mul2(pk2(acc0, acc1), scl2);
  }

  // stage B: one-sided Jacobi on M (accuracy-critical: keep 6 sweeps)
  jacobi1s2<6>(mm, lane);

  float ss2 = colnorm2(mm);

  // c = ||Z||_F = sqrt(sum sigma^4); idle lanes contribute 0
  float s4 = ss2 * ss2;
#pragma unroll
  for (int off = 16; off > 0; off >>= 1) s4 += __shfl_xor_sync(FULL, s4, off);
  float c = sqrtf(fmaxf(s4, 1e-30f));

  // per-column scalar: (sigma/sqrt(c))/sigma^2 = 1/(sigma*sqrt(c))
  float fscl = rsqrtf(fmaxf(ss2, 1e-24f) * c);

  u64 r[12];
  recompose24_2(mm, fscl, r, lane, tbuf[wid]);

  float *dst = out + (size_t)mIdx * 576;
  if (lane < 24) {
#pragma unroll
    for (int j = 0; j < 12; j++) {
      float e0, e1; upk2(r[j], e0, e1);
      dst[(2 * j) * 24 + lane]     = e0;
      dst[(2 * j + 1) * 24 + lane] = e1;
    }
  }
}

// ---------------------------------------------------------------------------
extern "C" void kernel_launch(void *const *d_in, const int *in_sizes, int n_in,
                              void *d_out, int out_size) {
  const float *x = nullptr, *A = nullptr, *Wm = nullptr;
  for (int i = 0; i < n_in; i++) {
    if (in_sizes[i] == 22118400)     x  = (const float *)d_in[i];
    else if (in_sizes[i] == 960000)  A  = (const float *)d_in[i];
    else if (in_sizes[i] == 576)     Wm = (const float *)d_in[i];
  }
  float *out = (float *)d_out;

  k_logm<<<NMAT / WPB, 128>>>(x);
  k_agg<<<1536, 800>>>(A);
  k_final<<<NMAT / WPB, 128>>>(Wm, out);
}